// round 1
// baseline (speedup 1.0000x reference)
#include <cuda_runtime.h>
#include <cuda_bf16.h>
#include <math.h>

#define T_DIM 64
#define B_DIM 4
#define INP_DIM 768
#define Q_DIM 384
#define E_DIM 384
#define DFF_DIM 1536
#define ROWS (T_DIM * B_DIM)   // 256

// ---------------- scratch (device globals; no allocation) ----------------
__device__ float g_mixed[ROWS * INP_DIM];
__device__ float g_forget[ROWS * Q_DIM];
__device__ float g_query[ROWS * Q_DIM];
__device__ float g_keyv[ROWS * Q_DIM];
__device__ float g_reset[ROWS * E_DIM];
__device__ float g_value[ROWS * E_DIM];
__device__ float g_out[ROWS * E_DIM];
__device__ float g_h[ROWS * INP_DIM];
__device__ float g_hn[ROWS * INP_DIM];
__device__ float g_gate[ROWS * DFF_DIM];

// ---------------- helpers ----------------
__device__ __forceinline__ float sigmoidf_(float x) { return 1.f / (1.f + expf(-x)); }
__device__ __forceinline__ float elu1f_(float x) { return x > 0.f ? x + 1.f : expf(x); }

// ---------------- K0: mixed = mu*inp + (1-mu)*lasts ----------------
__global__ void mixed_kernel(const float* __restrict__ inp,
                             const float* __restrict__ isf,
                             const float* __restrict__ init_inp,
                             const float* __restrict__ mu) {
    int r = blockIdx.x;           // 0..255
    int t = r >> 2;
    int b = r & 3;
    float m = (t == 0) ? 1.f : isf[r];
    for (int c = threadIdx.x; c < INP_DIM; c += blockDim.x) {
        float prev = (t == 0) ? 0.f : inp[(r - B_DIM) * INP_DIM + c];
        float lasts = prev + m * (init_inp[b * INP_DIM + c] - prev);
        float x = inp[r * INP_DIM + c];
        float muc = mu[c];
        g_mixed[r * INP_DIM + c] = muc * x + (1.f - muc) * lasts;
    }
}

// ---------------- generic 64x64 tiled fp32 GEMM ----------------
// C[M,N] = A[M,K] @ B[K,N], row-major; M,N multiples of 64; K multiple of 16.
// Epilogue functor: epi(row, col, acc)
template <class Epi>
__global__ __launch_bounds__(256) void gemm64(const float* __restrict__ A,
                                              const float* __restrict__ B,
                                              int K, int N, Epi epi) {
    __shared__ float As[16][68];   // transposed A tile, padded (16B-aligned rows)
    __shared__ float Bs[16][64];
    int tid = threadIdx.x;
    int tx = tid & 15, ty = tid >> 4;
    int row0 = blockIdx.y << 6, col0 = blockIdx.x << 6;

    int ar = tid >> 2, akc = (tid & 3) << 2;   // A: 64 rows x 16 k (float4/thread)
    int br = tid >> 4, bc = (tid & 15) << 2;   // B: 16 rows x 64 n

    const float* Aptr = A + (size_t)(row0 + ar) * K + akc;
    const float* Bptr = B + (size_t)br * N + col0 + bc;

    float acc[4][4];
#pragma unroll
    for (int i = 0; i < 4; i++)
#pragma unroll
        for (int j = 0; j < 4; j++) acc[i][j] = 0.f;

    for (int k0 = 0; k0 < K; k0 += 16) {
        float4 av = *(const float4*)(Aptr + k0);
        As[akc + 0][ar] = av.x;
        As[akc + 1][ar] = av.y;
        As[akc + 2][ar] = av.z;
        As[akc + 3][ar] = av.w;
        float4 bv = *(const float4*)(Bptr + (size_t)k0 * N);
        *(float4*)&Bs[br][bc] = bv;
        __syncthreads();
#pragma unroll
        for (int k = 0; k < 16; k++) {
            float4 a = *(const float4*)&As[k][ty << 2];
            float4 b = *(const float4*)&Bs[k][tx << 2];
            float aa[4] = {a.x, a.y, a.z, a.w};
            float bb[4] = {b.x, b.y, b.z, b.w};
#pragma unroll
            for (int i = 0; i < 4; i++)
#pragma unroll
                for (int j = 0; j < 4; j++) acc[i][j] = fmaf(aa[i], bb[j], acc[i][j]);
        }
        __syncthreads();
    }
#pragma unroll
    for (int i = 0; i < 4; i++)
#pragma unroll
        for (int j = 0; j < 4; j++)
            epi(row0 + (ty << 2) + i, col0 + (tx << 2) + j, acc[i][j]);
}

// ---------------- fused dual GEMM (FFN up): gate = silu(A@B1) * (A@B2) ----------------
__global__ __launch_bounds__(256) void gemm_dual(const float* __restrict__ A,
                                                 const float* __restrict__ B1,
                                                 const float* __restrict__ B2,
                                                 float* __restrict__ Cout,
                                                 int K, int N) {
    __shared__ float As[16][68];
    __shared__ float Bs1[16][64];
    __shared__ float Bs2[16][64];
    int tid = threadIdx.x;
    int tx = tid & 15, ty = tid >> 4;
    int row0 = blockIdx.y << 6, col0 = blockIdx.x << 6;

    int ar = tid >> 2, akc = (tid & 3) << 2;
    int br = tid >> 4, bc = (tid & 15) << 2;

    const float* Aptr = A + (size_t)(row0 + ar) * K + akc;
    const float* B1ptr = B1 + (size_t)br * N + col0 + bc;
    const float* B2ptr = B2 + (size_t)br * N + col0 + bc;

    float acc1[4][4], acc2[4][4];
#pragma unroll
    for (int i = 0; i < 4; i++)
#pragma unroll
        for (int j = 0; j < 4; j++) { acc1[i][j] = 0.f; acc2[i][j] = 0.f; }

    for (int k0 = 0; k0 < K; k0 += 16) {
        float4 av = *(const float4*)(Aptr + k0);
        As[akc + 0][ar] = av.x;
        As[akc + 1][ar] = av.y;
        As[akc + 2][ar] = av.z;
        As[akc + 3][ar] = av.w;
        float4 b1v = *(const float4*)(B1ptr + (size_t)k0 * N);
        *(float4*)&Bs1[br][bc] = b1v;
        float4 b2v = *(const float4*)(B2ptr + (size_t)k0 * N);
        *(float4*)&Bs2[br][bc] = b2v;
        __syncthreads();
#pragma unroll
        for (int k = 0; k < 16; k++) {
            float4 a = *(const float4*)&As[k][ty << 2];
            float4 b1 = *(const float4*)&Bs1[k][tx << 2];
            float4 b2 = *(const float4*)&Bs2[k][tx << 2];
            float aa[4] = {a.x, a.y, a.z, a.w};
            float bb1[4] = {b1.x, b1.y, b1.z, b1.w};
            float bb2[4] = {b2.x, b2.y, b2.z, b2.w};
#pragma unroll
            for (int i = 0; i < 4; i++)
#pragma unroll
                for (int j = 0; j < 4; j++) {
                    acc1[i][j] = fmaf(aa[i], bb1[j], acc1[i][j]);
                    acc2[i][j] = fmaf(aa[i], bb2[j], acc2[i][j]);
                }
        }
        __syncthreads();
    }
#pragma unroll
    for (int i = 0; i < 4; i++)
#pragma unroll
        for (int j = 0; j < 4; j++) {
            int r = row0 + (ty << 2) + i;
            int c = col0 + (tx << 2) + j;
            float x = acc1[i][j];
            float sil = x / (1.f + expf(-x));
            Cout[(size_t)r * N + c] = sil * acc2[i][j];
        }
}

// ---------------- epilogue functors ----------------
struct EpiForget {
    const float* drops;
    float* outF;
    __device__ __forceinline__ void operator()(int r, int c, float v) const {
        float s = sigmoidf_(v);
        outF[r * Q_DIM + c] = (s - 1.f) * drops[r] + 1.f;
    }
};

struct EpiParts {
    const float* drops;
    __device__ __forceinline__ void operator()(int r, int c, float v) const {
        v *= drops[r];
        if (c < Q_DIM) g_query[r * Q_DIM + c] = elu1f_(v);
        else if (c < 2 * Q_DIM) g_keyv[r * Q_DIM + (c - Q_DIM)] = elu1f_(v);
        else if (c < 2 * Q_DIM + E_DIM) g_reset[r * E_DIM + (c - 2 * Q_DIM)] = v;
        else g_value[r * E_DIM + (c - 2 * Q_DIM - E_DIM)] = v;
    }
};

struct EpiProj {
    const float* inp;
    __device__ __forceinline__ void operator()(int r, int c, float v) const {
        g_h[r * INP_DIM + c] = v + inp[r * INP_DIM + c];
    }
};

struct EpiPlain {
    float* C;
    int N;
    __device__ __forceinline__ void operator()(int r, int c, float v) const {
        C[(size_t)r * N + c] = v;
    }
};

// ---------------- K2b: value = sigmoid(reset) * value ----------------
__global__ void split_kernel() {
    int i = blockIdx.x * blockDim.x + threadIdx.x;
    if (i < ROWS * E_DIM) g_value[i] = sigmoidf_(g_reset[i]) * g_value[i];
}

// ---------------- K3: gated linear scan over T, register-resident state ----------------
// grid (12, 4): blockIdx.x = e-block (32 wide), blockIdx.y = b. 256 threads.
// thread layout: lane = q-group (q = lane + 32k, k<12), warp eg owns e = e0 + eg*4 + j.
__global__ __launch_bounds__(256) void scan_kernel(const float* __restrict__ isf,
                                                   const float* __restrict__ init_state) {
    __shared__ float sf[Q_DIM], sk[Q_DIM], sq[Q_DIM], sv[32];
    int b = blockIdx.y;
    int e0 = blockIdx.x * 32;
    int tid = threadIdx.x;
    int lane = tid & 31;
    int eg = tid >> 5;   // warp id 0..7

    float s[12][4];
#pragma unroll
    for (int k = 0; k < 12; k++)
#pragma unroll
        for (int j = 0; j < 4; j++) s[k][j] = 0.f;

    for (int t = 0; t < T_DIM; t++) {
        int r = t * B_DIM + b;
        const float* fb = g_forget + r * Q_DIM;
        const float* kb = g_keyv + r * Q_DIM;
        const float* qb = g_query + r * Q_DIM;
        for (int i = tid; i < Q_DIM; i += 256) {
            sf[i] = fb[i];
            sk[i] = kb[i];
            sq[i] = qb[i];
        }
        if (tid < 32) sv[tid] = g_value[r * E_DIM + e0 + tid];
        __syncthreads();

        float m = (t == 0) ? 1.f : isf[r];
        bool reset = m > 0.f;
        float vj[4];
#pragma unroll
        for (int j = 0; j < 4; j++) vj[j] = sv[eg * 4 + j];

        float o[4] = {0.f, 0.f, 0.f, 0.f};
#pragma unroll
        for (int k = 0; k < 12; k++) {
            int q = lane + 32 * k;
            float f = sf[q];
            float kv = sk[q];
            float qr = sq[q];
#pragma unroll
            for (int j = 0; j < 4; j++) {
                float base = s[k][j];
                if (reset)
                    base = init_state[((size_t)b * Q_DIM + q) * E_DIM + e0 + eg * 4 + j];
                float ns = fmaf(f, base, kv * vj[j]);
                s[k][j] = ns;
                o[j] = fmaf(qr, ns, o[j]);
            }
        }
        // reduce over 32 q-lanes per warp
#pragma unroll
        for (int j = 0; j < 4; j++) {
#pragma unroll
            for (int off = 16; off; off >>= 1)
                o[j] += __shfl_xor_sync(0xffffffffu, o[j], off);
        }
        if (lane == 0) {
#pragma unroll
            for (int j = 0; j < 4; j++)
                g_out[r * E_DIM + e0 + eg * 4 + j] = o[j];
        }
        __syncthreads();
    }
}

// ---------------- K4a: RMS norm over E (in place on g_out) ----------------
__global__ __launch_bounds__(128) void rms_kernel(const float* __restrict__ rms_w) {
    int r = blockIdx.x;
    int tid = threadIdx.x;
    int lane = tid & 31, wid = tid >> 5;
    __shared__ float red[4];
    float ss = 0.f;
    for (int i = tid; i < E_DIM; i += 128) {
        float v = g_out[r * E_DIM + i];
        ss += v * v;
    }
#pragma unroll
    for (int off = 16; off; off >>= 1) ss += __shfl_xor_sync(0xffffffffu, ss, off);
    if (lane == 0) red[wid] = ss;
    __syncthreads();
    if (tid == 0) {
        float tot = red[0] + red[1] + red[2] + red[3];
        red[0] = rsqrtf(tot * (1.f / E_DIM) + 1e-6f);
    }
    __syncthreads();
    float scale = red[0];
    for (int i = tid; i < E_DIM; i += 128) {
        g_out[r * E_DIM + i] = g_out[r * E_DIM + i] * scale * rms_w[i];
    }
}

// ---------------- K4c: LayerNorm over INP: g_h -> g_hn ----------------
__global__ __launch_bounds__(256) void ln_kernel(const float* __restrict__ ln_w,
                                                 const float* __restrict__ ln_b) {
    int r = blockIdx.x;
    int tid = threadIdx.x;
    int lane = tid & 31, wid = tid >> 5;
    __shared__ float red1[8], red2[8], stats[2];
    float s1 = 0.f, s2 = 0.f;
    for (int i = tid; i < INP_DIM; i += 256) {
        float v = g_h[r * INP_DIM + i];
        s1 += v;
        s2 += v * v;
    }
#pragma unroll
    for (int off = 16; off; off >>= 1) {
        s1 += __shfl_xor_sync(0xffffffffu, s1, off);
        s2 += __shfl_xor_sync(0xffffffffu, s2, off);
    }
    if (lane == 0) { red1[wid] = s1; red2[wid] = s2; }
    __syncthreads();
    if (tid == 0) {
        float t1 = 0.f, t2 = 0.f;
        for (int w = 0; w < 8; w++) { t1 += red1[w]; t2 += red2[w]; }
        float mu = t1 * (1.f / INP_DIM);
        float var = t2 * (1.f / INP_DIM) - mu * mu;
        stats[0] = mu;
        stats[1] = rsqrtf(var + 1e-5f);
    }
    __syncthreads();
    float mu = stats[0], inv = stats[1];
    for (int i = tid; i < INP_DIM; i += 256) {
        float v = g_h[r * INP_DIM + i];
        g_hn[r * INP_DIM + i] = (v - mu) * inv * ln_w[i] + ln_b[i];
    }
}

// ---------------- launch ----------------
extern "C" void kernel_launch(void* const* d_in, const int* in_sizes, int n_in,
                              void* d_out, int out_size) {
    const float* inp        = (const float*)d_in[0];
    const float* is_first   = (const float*)d_in[1];
    const float* drops      = (const float*)d_in[2];
    const float* init_inp   = (const float*)d_in[3];
    const float* init_state = (const float*)d_in[4];
    const float* mix_mu     = (const float*)d_in[5];
    const float* mix_W      = (const float*)d_in[6];
    const float* layer_W    = (const float*)d_in[7];
    const float* proj_W     = (const float*)d_in[8];
    const float* rms_w      = (const float*)d_in[9];
    const float* ln_w       = (const float*)d_in[10];
    const float* ln_b       = (const float*)d_in[11];
    const float* ffn_W1     = (const float*)d_in[12];
    const float* ffn_W2     = (const float*)d_in[13];
    const float* ffn_W3     = (const float*)d_in[14];
    float* out = (float*)d_out;

    float *p_mixed, *p_forget, *p_out, *p_hn, *p_gate;
    cudaGetSymbolAddress((void**)&p_mixed, g_mixed);
    cudaGetSymbolAddress((void**)&p_forget, g_forget);
    cudaGetSymbolAddress((void**)&p_out, g_out);
    cudaGetSymbolAddress((void**)&p_hn, g_hn);
    cudaGetSymbolAddress((void**)&p_gate, g_gate);

    // K0: mixed
    mixed_kernel<<<ROWS, 256>>>(inp, is_first, init_inp, mix_mu);

    // K1: forget = (sigmoid(mixed @ mix_W) - 1) * drops + 1
    {
        EpiForget epi{drops, p_forget};
        gemm64<EpiForget><<<dim3(Q_DIM / 64, ROWS / 64), 256>>>(p_mixed, mix_W, INP_DIM, Q_DIM, epi);
    }

    // K2: parts = inp @ layer_W * drops  (split into query/keyv/reset/value)
    {
        EpiParts epi{drops};
        gemm64<EpiParts><<<dim3((2 * Q_DIM + 2 * E_DIM) / 64, ROWS / 64), 256>>>(
            inp, layer_W, INP_DIM, 2 * Q_DIM + 2 * E_DIM, epi);
    }

    // K2b: value = sigmoid(reset) * value
    split_kernel<<<(ROWS * E_DIM) / 256, 256>>>();

    // K3: scan -> g_out
    scan_kernel<<<dim3(E_DIM / 32, B_DIM), 256>>>(is_first, init_state);

    // K4a: RMS norm
    rms_kernel<<<ROWS, 128>>>(rms_w);

    // K4b: h = inp + out @ proj_W
    {
        EpiProj epi{inp};
        gemm64<EpiProj><<<dim3(INP_DIM / 64, ROWS / 64), 256>>>(p_out, proj_W, E_DIM, INP_DIM, epi);
    }

    // K4c: LayerNorm
    ln_kernel<<<ROWS, 256>>>(ln_w, ln_b);

    // K5a: gate = silu(hn @ W1) * (hn @ W2)
    gemm_dual<<<dim3(DFF_DIM / 64, ROWS / 64), 256>>>(p_hn, ffn_W1, ffn_W2, p_gate, INP_DIM, DFF_DIM);

    // K5b: out = gate @ W3
    {
        EpiPlain epi{out, INP_DIM};
        gemm64<EpiPlain><<<dim3(INP_DIM / 64, ROWS / 64), 256>>>(p_gate, ffn_W3, DFF_DIM, INP_DIM, epi);
    }
}

// round 2
// speedup vs baseline: 2.2347x; 2.2347x over previous
#include <cuda_runtime.h>
#include <math.h>

typedef unsigned long long ull;

#define T_DIM 64
#define B_DIM 4
#define INP_DIM 768
#define Q_DIM 384
#define E_DIM 384
#define DFF_DIM 1536
#define ROWS 256          // T*B
#define S1_COLS 1920      // 384 forget + 1536 parts

#define S1_SPLIT 2        // K=768 -> 384 chunks
#define PROJ_SPLIT 2      // K=384 -> 192
#define UP_SPLIT 2        // K=768 -> 384 (x2 for W1/W2)
#define DOWN_SPLIT 6      // K=1536 -> 256

// ---------------- scratch (device globals; no allocation) ----------------
__device__ float g_mixed[ROWS * INP_DIM];
__device__ float g_forget[ROWS * Q_DIM];
__device__ float g_query[ROWS * Q_DIM];
__device__ float g_keyv[ROWS * Q_DIM];
__device__ float g_value[ROWS * E_DIM];
__device__ float g_out[ROWS * E_DIM];
__device__ float g_hn[ROWS * INP_DIM];
__device__ float g_gate[ROWS * DFF_DIM];
__device__ float g_p1[S1_SPLIT][ROWS][S1_COLS];
__device__ float g_p2[PROJ_SPLIT][ROWS][INP_DIM];
__device__ float g_p3[2 * UP_SPLIT][ROWS][DFF_DIM];
__device__ float g_p4[DOWN_SPLIT][ROWS][INP_DIM];

// ---------------- helpers ----------------
__device__ __forceinline__ float sigmoidf_(float x) { return 1.f / (1.f + expf(-x)); }
__device__ __forceinline__ float elu1f_(float x) { return x > 0.f ? x + 1.f : expf(x); }

__device__ __forceinline__ ull ffma2(ull a, ull b, ull c) {
    ull d;
    asm("fma.rn.f32x2 %0, %1, %2, %3;" : "=l"(d) : "l"(a), "l"(b), "l"(c));
    return d;
}
__device__ __forceinline__ ull pack2(float lo, float hi) {
    ull d;
    asm("mov.b64 %0, {%1, %2};" : "=l"(d) : "f"(lo), "f"(hi));
    return d;
}
__device__ __forceinline__ void unpack2(ull v, float& lo, float& hi) {
    asm("mov.b64 {%0, %1}, %2;" : "=f"(lo), "=f"(hi) : "l"(v));
}

// ---------------- K0: mixed = mu*inp + (1-mu)*lasts ----------------
__global__ void mixed_kernel(const float* __restrict__ inp,
                             const float* __restrict__ isf,
                             const float* __restrict__ init_inp,
                             const float* __restrict__ mu) {
    int r = blockIdx.x;
    int t = r >> 2;
    int b = r & 3;
    float m = (t == 0) ? 1.f : isf[r];
    for (int c = threadIdx.x; c < INP_DIM; c += blockDim.x) {
        float prev = (t == 0) ? 0.f : inp[(r - B_DIM) * INP_DIM + c];
        float lasts = prev + m * (init_inp[b * INP_DIM + c] - prev);
        float x = inp[r * INP_DIM + c];
        float muc = mu[c];
        g_mixed[r * INP_DIM + c] = muc * x + (1.f - muc) * lasts;
    }
}

// ---------------- double-buffered f32x2 GEMM tile (64x64, 256 threads) ----
struct GemmSmem {
    __align__(16) float As[2][16][68];   // [buf][k][row]
    __align__(16) float Bs[2][16][64];   // [buf][k][col]
};

__device__ __forceinline__ void gemm_tile(
    GemmSmem& sm,
    const float* __restrict__ A, int lda,
    const float* __restrict__ B, int ldb,
    int row0, int col0, int kOff, int nt,
    float* __restrict__ C, int ldc) {
    int tid = threadIdx.x;
    int tx = tid & 15, ty = tid >> 4;
    int ar = tid >> 2, akc = (tid & 3) << 2;    // A loader: 64 rows x 16 k
    int br = tid >> 4, bc = (tid & 15) << 2;    // B loader: 16 k x 64 cols

    const float* Ap = A + (size_t)(row0 + ar) * lda + kOff + akc;
    const float* Bp = B + (size_t)(kOff + br) * ldb + col0 + bc;

    float4 av = *(const float4*)Ap;
    float4 bv = *(const float4*)Bp;
    sm.As[0][akc + 0][ar] = av.x;
    sm.As[0][akc + 1][ar] = av.y;
    sm.As[0][akc + 2][ar] = av.z;
    sm.As[0][akc + 3][ar] = av.w;
    *(float4*)&sm.Bs[0][br][bc] = bv;
    __syncthreads();

    ull acc[2][4];
#pragma unroll
    for (int p = 0; p < 2; p++)
#pragma unroll
        for (int j = 0; j < 4; j++) acc[p][j] = pack2(0.f, 0.f);

    for (int t = 0; t < nt; t++) {
        int cur = t & 1;
        if (t + 1 < nt) {
            av = *(const float4*)(Ap + (t + 1) * 16);
            bv = *(const float4*)(Bp + (size_t)(t + 1) * 16 * ldb);
        }
#pragma unroll
        for (int k = 0; k < 16; k++) {
            ull a01 = *(const ull*)&sm.As[cur][k][ty << 2];
            ull a23 = *(const ull*)&sm.As[cur][k][(ty << 2) + 2];
            float4 b = *(const float4*)&sm.Bs[cur][k][tx << 2];
            ull b0 = pack2(b.x, b.x);
            ull b1 = pack2(b.y, b.y);
            ull b2 = pack2(b.z, b.z);
            ull b3 = pack2(b.w, b.w);
            acc[0][0] = ffma2(a01, b0, acc[0][0]);
            acc[1][0] = ffma2(a23, b0, acc[1][0]);
            acc[0][1] = ffma2(a01, b1, acc[0][1]);
            acc[1][1] = ffma2(a23, b1, acc[1][1]);
            acc[0][2] = ffma2(a01, b2, acc[0][2]);
            acc[1][2] = ffma2(a23, b2, acc[1][2]);
            acc[0][3] = ffma2(a01, b3, acc[0][3]);
            acc[1][3] = ffma2(a23, b3, acc[1][3]);
        }
        if (t + 1 < nt) {
            int nx = cur ^ 1;
            sm.As[nx][akc + 0][ar] = av.x;
            sm.As[nx][akc + 1][ar] = av.y;
            sm.As[nx][akc + 2][ar] = av.z;
            sm.As[nx][akc + 3][ar] = av.w;
            *(float4*)&sm.Bs[nx][br][bc] = bv;
        }
        __syncthreads();
    }

#pragma unroll
    for (int j = 0; j < 4; j++) {
        int cc = col0 + (tx << 2) + j;
        float lo, hi;
        unpack2(acc[0][j], lo, hi);
        C[(size_t)(row0 + (ty << 2) + 0) * ldc + cc] = lo;
        C[(size_t)(row0 + (ty << 2) + 1) * ldc + cc] = hi;
        unpack2(acc[1][j], lo, hi);
        C[(size_t)(row0 + (ty << 2) + 2) * ldc + cc] = lo;
        C[(size_t)(row0 + (ty << 2) + 3) * ldc + cc] = hi;
    }
}

// ---------------- stage1: forget + parts partials in one launch ----------
__global__ __launch_bounds__(256) void stage1_kernel(const float* __restrict__ inp,
                                                     const float* __restrict__ mix_W,
                                                     const float* __restrict__ layer_W) {
    __shared__ GemmSmem sm;
    int bx = blockIdx.x, row0 = blockIdx.y * 64, z = blockIdx.z;
    int kOff = z * (INP_DIM / S1_SPLIT);
    const int nt = (INP_DIM / S1_SPLIT) / 16;
    float* C = &g_p1[z][0][0];
    if (bx < Q_DIM / 64)
        gemm_tile(sm, g_mixed, INP_DIM, mix_W, Q_DIM, row0, bx * 64, kOff, nt, C, S1_COLS);
    else
        gemm_tile(sm, inp, INP_DIM, layer_W, 1536, row0, (bx - Q_DIM / 64) * 64, kOff, nt,
                  C + Q_DIM, S1_COLS);
}

// ---------------- epi1: reduce partials + nonlinearity ----------
__global__ void epi1_kernel(const float* __restrict__ drops) {
    int r = blockIdx.x, j = threadIdx.x;   // 384 threads
    float d = drops[r];
    const float* p0 = &g_p1[0][r][0];
    const float* p1 = &g_p1[1][r][0];
    float fs = p0[j] + p1[j];
    g_forget[r * Q_DIM + j] = (sigmoidf_(fs) - 1.f) * d + 1.f;
    float qs = (p0[384 + j] + p1[384 + j]) * d;
    g_query[r * Q_DIM + j] = elu1f_(qs);
    float ks = (p0[768 + j] + p1[768 + j]) * d;
    g_keyv[r * Q_DIM + j] = elu1f_(ks);
    float rs = (p0[1152 + j] + p1[1152 + j]) * d;
    float vs = (p0[1536 + j] + p1[1536 + j]) * d;
    g_value[r * E_DIM + j] = sigmoidf_(rs) * vs;
}

// ---------------- scan: register-resident, no smem, no syncs -------------
// grid (24, 4), 128 threads. warp w owns e = e0 + w*4 + {0..3}, lane = q mod 32.
__device__ __forceinline__ void scan_load(int t, int b, int ebase, int lane,
                                          const float* __restrict__ isf, float& m,
                                          float (&f)[12], float (&k)[12],
                                          float (&q)[12], float (&v)[4]) {
    int r = t * B_DIM + b;
    const float* fp = g_forget + (size_t)r * Q_DIM + lane;
    const float* kp = g_keyv + (size_t)r * Q_DIM + lane;
    const float* qp = g_query + (size_t)r * Q_DIM + lane;
#pragma unroll
    for (int kk = 0; kk < 12; kk++) {
        f[kk] = fp[32 * kk];
        k[kk] = kp[32 * kk];
        q[kk] = qp[32 * kk];
    }
    const float* vp = g_value + (size_t)r * E_DIM + ebase;
#pragma unroll
    for (int j = 0; j < 4; j++) v[j] = vp[j];
    m = isf[r];
}

__device__ __forceinline__ void scan_step(int t, int b, int ebase, int lane,
                                          const float* __restrict__ init_state, float m,
                                          const float (&f)[12], const float (&k)[12],
                                          const float (&q)[12], const float (&v)[4],
                                          float (&s)[12][4]) {
    int r = t * B_DIM + b;
    bool rst = (t == 0) || (m > 0.f);
    if (rst) {
#pragma unroll
        for (int kk = 0; kk < 12; kk++) {
            int qi = lane + 32 * kk;
            const float* ip = init_state + ((size_t)b * Q_DIM + qi) * E_DIM + ebase;
#pragma unroll
            for (int j = 0; j < 4; j++) s[kk][j] = ip[j];
        }
    }
    float o0 = 0.f, o1 = 0.f, o2 = 0.f, o3 = 0.f;
#pragma unroll
    for (int kk = 0; kk < 12; kk++) {
        float ff = f[kk], kv = k[kk], qr = q[kk];
        float n0 = fmaf(ff, s[kk][0], kv * v[0]); s[kk][0] = n0; o0 = fmaf(qr, n0, o0);
        float n1 = fmaf(ff, s[kk][1], kv * v[1]); s[kk][1] = n1; o1 = fmaf(qr, n1, o1);
        float n2 = fmaf(ff, s[kk][2], kv * v[2]); s[kk][2] = n2; o2 = fmaf(qr, n2, o2);
        float n3 = fmaf(ff, s[kk][3], kv * v[3]); s[kk][3] = n3; o3 = fmaf(qr, n3, o3);
    }
#pragma unroll
    for (int off = 16; off; off >>= 1) {
        o0 += __shfl_xor_sync(0xffffffffu, o0, off);
        o1 += __shfl_xor_sync(0xffffffffu, o1, off);
        o2 += __shfl_xor_sync(0xffffffffu, o2, off);
        o3 += __shfl_xor_sync(0xffffffffu, o3, off);
    }
    if (lane == 0) {
        float* op = g_out + (size_t)r * E_DIM + ebase;
        op[0] = o0; op[1] = o1; op[2] = o2; op[3] = o3;
    }
}

__global__ __launch_bounds__(128) void scan_kernel(const float* __restrict__ isf,
                                                   const float* __restrict__ init_state) {
    int b = blockIdx.y;
    int e0 = blockIdx.x * 16;
    int tid = threadIdx.x, lane = tid & 31, w = tid >> 5;
    int ebase = e0 + w * 4;

    float s[12][4];
    float fA[12], kA[12], qA[12], vA[4], mA;
    float fB[12], kB[12], qB[12], vB[4], mB;

    scan_load(0, b, ebase, lane, isf, mA, fA, kA, qA, vA);
    for (int t = 0; t < T_DIM; t += 2) {
        if (t + 1 < T_DIM) scan_load(t + 1, b, ebase, lane, isf, mB, fB, kB, qB, vB);
        scan_step(t, b, ebase, lane, init_state, mA, fA, kA, qA, vA, s);
        if (t + 2 < T_DIM) scan_load(t + 2, b, ebase, lane, isf, mA, fA, kA, qA, vA);
        scan_step(t + 1, b, ebase, lane, init_state, mB, fB, kB, qB, vB, s);
    }
}

// ---------------- RMS norm over E (in place on g_out) ----------------
__global__ __launch_bounds__(128) void rms_kernel(const float* __restrict__ rms_w) {
    int r = blockIdx.x;
    int tid = threadIdx.x;
    int lane = tid & 31, wid = tid >> 5;
    __shared__ float red[4];
    float ss = 0.f;
    for (int i = tid; i < E_DIM; i += 128) {
        float v = g_out[r * E_DIM + i];
        ss += v * v;
    }
#pragma unroll
    for (int off = 16; off; off >>= 1) ss += __shfl_xor_sync(0xffffffffu, ss, off);
    if (lane == 0) red[wid] = ss;
    __syncthreads();
    if (tid == 0) red[0] = rsqrtf((red[0] + red[1] + red[2] + red[3]) * (1.f / E_DIM) + 1e-6f);
    __syncthreads();
    float scale = red[0];
    for (int i = tid; i < E_DIM; i += 128)
        g_out[r * E_DIM + i] = g_out[r * E_DIM + i] * scale * rms_w[i];
}

// ---------------- proj GEMM partials ----------------
__global__ __launch_bounds__(256) void proj_kernel(const float* __restrict__ proj_W) {
    __shared__ GemmSmem sm;
    int z = blockIdx.z;
    gemm_tile(sm, g_out, E_DIM, proj_W, INP_DIM, blockIdx.y * 64, blockIdx.x * 64,
              z * (E_DIM / PROJ_SPLIT), (E_DIM / PROJ_SPLIT) / 16, &g_p2[z][0][0], INP_DIM);
}

// ---------------- projLN: h = inp + sum(partials); LayerNorm -> g_hn -----
__global__ __launch_bounds__(256) void projln_kernel(const float* __restrict__ inp,
                                                     const float* __restrict__ ln_w,
                                                     const float* __restrict__ ln_b) {
    __shared__ float sh[INP_DIM];
    __shared__ float red1[8], red2[8], stats[2];
    int r = blockIdx.x, tid = threadIdx.x, lane = tid & 31, wid = tid >> 5;
    float s1 = 0.f, s2 = 0.f;
    for (int c = tid; c < INP_DIM; c += 256) {
        float h = g_p2[0][r][c] + g_p2[1][r][c] + inp[r * INP_DIM + c];
        sh[c] = h;
        s1 += h;
        s2 += h * h;
    }
#pragma unroll
    for (int off = 16; off; off >>= 1) {
        s1 += __shfl_xor_sync(0xffffffffu, s1, off);
        s2 += __shfl_xor_sync(0xffffffffu, s2, off);
    }
    if (lane == 0) { red1[wid] = s1; red2[wid] = s2; }
    __syncthreads();
    if (tid == 0) {
        float t1 = 0.f, t2 = 0.f;
        for (int w = 0; w < 8; w++) { t1 += red1[w]; t2 += red2[w]; }
        float mu = t1 * (1.f / INP_DIM);
        float var = t2 * (1.f / INP_DIM) - mu * mu;
        stats[0] = mu;
        stats[1] = rsqrtf(var + 1e-5f);
    }
    __syncthreads();
    float mu = stats[0], inv = stats[1];
    for (int c = tid; c < INP_DIM; c += 256)
        g_hn[r * INP_DIM + c] = (sh[c] - mu) * inv * ln_w[c] + ln_b[c];
}

// ---------------- FFN up partials (W1 / W2 via grid.z) ----------------
__global__ __launch_bounds__(256) void ffnup_kernel(const float* __restrict__ W1,
                                                    const float* __restrict__ W2) {
    __shared__ GemmSmem sm;
    int z = blockIdx.z;
    int which = z >> 1, sp = z & 1;
    const float* B = which ? W2 : W1;
    gemm_tile(sm, g_hn, INP_DIM, B, DFF_DIM, blockIdx.y * 64, blockIdx.x * 64,
              sp * (INP_DIM / UP_SPLIT), (INP_DIM / UP_SPLIT) / 16, &g_p3[z][0][0], DFF_DIM);
}

// ---------------- silu-mul reduce ----------------
__global__ void silumul_kernel() {
    int i = blockIdx.x * blockDim.x + threadIdx.x;
    const float* b = &g_p3[0][0][0];
    const size_t st = (size_t)ROWS * DFF_DIM;
    float u = b[i] + b[st + i];
    float g = b[2 * st + i] + b[3 * st + i];
    g_gate[i] = u * (1.f / (1.f + expf(-u))) * g;
}

// ---------------- down GEMM partials ----------------
__global__ __launch_bounds__(256) void down_kernel(const float* __restrict__ W3) {
    __shared__ GemmSmem sm;
    int z = blockIdx.z;
    gemm_tile(sm, g_gate, DFF_DIM, W3, INP_DIM, blockIdx.y * 64, blockIdx.x * 64,
              z * (DFF_DIM / DOWN_SPLIT), (DFF_DIM / DOWN_SPLIT) / 16, &g_p4[z][0][0], INP_DIM);
}

// ---------------- final reduce to d_out ----------------
__global__ void reduceout_kernel(float* __restrict__ out) {
    int i = blockIdx.x * blockDim.x + threadIdx.x;
    const float* b = &g_p4[0][0][0];
    const size_t st = (size_t)ROWS * INP_DIM;
    float s = 0.f;
#pragma unroll
    for (int z = 0; z < DOWN_SPLIT; z++) s += b[z * st + i];
    out[i] = s;
}

// ---------------- launch ----------------
extern "C" void kernel_launch(void* const* d_in, const int* in_sizes, int n_in,
                              void* d_out, int out_size) {
    const float* inp        = (const float*)d_in[0];
    const float* is_first   = (const float*)d_in[1];
    const float* drops      = (const float*)d_in[2];
    const float* init_inp   = (const float*)d_in[3];
    const float* init_state = (const float*)d_in[4];
    const float* mix_mu     = (const float*)d_in[5];
    const float* mix_W      = (const float*)d_in[6];
    const float* layer_W    = (const float*)d_in[7];
    const float* proj_W     = (const float*)d_in[8];
    const float* rms_w      = (const float*)d_in[9];
    const float* ln_w       = (const float*)d_in[10];
    const float* ln_b       = (const float*)d_in[11];
    const float* ffn_W1     = (const float*)d_in[12];
    const float* ffn_W2     = (const float*)d_in[13];
    const float* ffn_W3     = (const float*)d_in[14];
    float* out = (float*)d_out;

    mixed_kernel<<<ROWS, 256>>>(inp, is_first, init_inp, mix_mu);
    stage1_kernel<<<dim3(30, 4, S1_SPLIT), 256>>>(inp, mix_W, layer_W);
    epi1_kernel<<<ROWS, 384>>>(drops);
    scan_kernel<<<dim3(E_DIM / 16, B_DIM), 128>>>(is_first, init_state);
    rms_kernel<<<ROWS, 128>>>(rms_w);
    proj_kernel<<<dim3(INP_DIM / 64, ROWS / 64, PROJ_SPLIT), 256>>>(proj_W);
    projln_kernel<<<ROWS, 256>>>(inp, ln_w, ln_b);
    ffnup_kernel<<<dim3(DFF_DIM / 64, ROWS / 64, 2 * UP_SPLIT), 256>>>(ffn_W1, ffn_W2);
    silumul_kernel<<<(ROWS * DFF_DIM) / 256, 256>>>();
    down_kernel<<<dim3(INP_DIM / 64, ROWS / 64, DOWN_SPLIT), 256>>>(ffn_W3);
    reduceout_kernel<<<(ROWS * INP_DIM) / 256, 256>>>(out);
}